// round 15
// baseline (speedup 1.0000x reference)
#include <cuda_runtime.h>
#include <cuda_bf16.h>
#include <cstdint>

#define NN    4096
#define FIN   512
#define FHID  256
#define FCLS  16
#define NHD   4

// ---------------- scratch (static device globals) ---------------------------
__device__ __nv_bfloat16  g_h1b  [NHD*NN*FHID];        // 8 MB
__device__ __nv_bfloat16  g_out1b[NHD*NN*FHID];        // 8 MB
__device__ __nv_bfloat16  g_xb  [NN*FIN];              // 4 MB
__device__ __nv_bfloat16  g_W1b [NHD*FIN*FHID];        // 1 MB
__device__ unsigned       g_adjbits[(size_t)NN*NN/32]; // 2 MB
__device__ __nv_bfloat16  g_edB [NHD*NN];              // rank-1 tables (bf16)
__device__ __nv_bfloat162 g_B12B[NHD*NN];
__device__ float g_esrc1[NHD*NN], g_edst1[NHD*NN];     // atomically accumulated
__device__ float g_A11[NHD*NN], g_A21[NHD*NN];
__device__ float g_h2[NN*FCLS];
__device__ float g_esrc2[NN], g_edst2[NN];
__device__ float g_A12[NN], g_A22[NN], g_B12[NN], g_B22[NN];

// ---------------- PTX helpers ------------------------------------------------
__device__ __forceinline__ uint32_t smem_u32(const void* p) {
    uint32_t a;
    asm("{ .reg .u64 t; cvta.to.shared.u64 t, %1; cvt.u32.u64 %0, t; }"
        : "=r"(a) : "l"(p));
    return a;
}
__device__ __forceinline__ void mma16816(float* c, const uint32_t* a, const uint32_t* b) {
    asm volatile("mma.sync.aligned.m16n8k16.row.col.f32.bf16.bf16.f32 "
                 "{%0,%1,%2,%3}, {%4,%5,%6,%7}, {%8,%9}, {%0,%1,%2,%3};\n"
                 : "+f"(c[0]), "+f"(c[1]), "+f"(c[2]), "+f"(c[3])
                 : "r"(a[0]), "r"(a[1]), "r"(a[2]), "r"(a[3]),
                   "r"(b[0]), "r"(b[1]));
}
__device__ __forceinline__ void ldsm_x4(uint32_t* r, const void* p) {
    uint32_t a = smem_u32(p);
    asm volatile("ldmatrix.sync.aligned.m8n8.x4.shared.b16 {%0,%1,%2,%3}, [%4];"
                 : "=r"(r[0]), "=r"(r[1]), "=r"(r[2]), "=r"(r[3]) : "r"(a));
}
__device__ __forceinline__ void ldsm_x4_t(uint32_t* r, const void* p) {
    uint32_t a = smem_u32(p);
    asm volatile("ldmatrix.sync.aligned.m8n8.x4.trans.shared.b16 {%0,%1,%2,%3}, [%4];"
                 : "=r"(r[0]), "=r"(r[1]), "=r"(r[2]), "=r"(r[3]) : "r"(a));
}
__device__ __forceinline__ void cpa16(void* s, const void* g) {
    uint32_t sa = smem_u32(s);
    asm volatile("cp.async.cg.shared.global [%0], [%1], 16;\n" :: "r"(sa), "l"(g));
}
#define CP_COMMIT asm volatile("cp.async.commit_group;\n" ::: "memory")
#define CP_WAIT0  asm volatile("cp.async.wait_group 0;\n" ::: "memory")

// ---------------- k1 mma micro-kernel (128x128, 4x2 warps, BK=32) -----------
__device__ __forceinline__ void mma_step(const __nv_bfloat16* As, const __nv_bfloat16* Bs,
                                         int wm, int wn, int lane, float acc[2][8][4]) {
#pragma unroll
    for (int s = 0; s < 2; s++) {
        uint32_t a[2][4];
        const int lr = lane & 15, lc = lane >> 4;
#pragma unroll
        for (int t = 0; t < 2; t++)
            ldsm_x4(a[t], &As[(wm * 32 + t * 16 + lr) * 40 + s * 16 + lc * 8]);
        uint32_t b[8][2];
        const int brow = s * 16 + (lane & 7) + (lane & 8);
        const int bco  = (lane & 16) >> 1;
#pragma unroll
        for (int p = 0; p < 4; p++) {
            uint32_t r[4];
            ldsm_x4_t(r, &Bs[brow * 136 + wn * 64 + p * 16 + bco]);
            b[2*p][0] = r[0]; b[2*p][1] = r[1];
            b[2*p+1][0] = r[2]; b[2*p+1][1] = r[3];
        }
#pragma unroll
        for (int t = 0; t < 2; t++)
#pragma unroll
            for (int j = 0; j < 8; j++)
                mma16816(acc[t][j], a[t], b[j]);
    }
}

// ---------------- attention mma micro-kernel (128x128, 4x2 warps, BK=64) ----
__device__ __forceinline__ void mma_step64(const __nv_bfloat16* As, const __nv_bfloat16* Bs,
                                           int wm, int wn, int lane, float acc[2][8][4]) {
#pragma unroll
    for (int s = 0; s < 4; s++) {
        uint32_t a[2][4];
        const int lr = lane & 15, lc = lane >> 4;
#pragma unroll
        for (int t = 0; t < 2; t++)
            ldsm_x4(a[t], &As[(wm * 32 + t * 16 + lr) * 72 + s * 16 + lc * 8]);
        uint32_t b[8][2];
        const int brow = s * 16 + (lane & 7) + (lane & 8);
        const int bco  = (lane & 16) >> 1;
#pragma unroll
        for (int p = 0; p < 4; p++) {
            uint32_t r[4];
            ldsm_x4_t(r, &Bs[brow * 136 + wn * 64 + p * 16 + bco]);
            b[2*p][0] = r[0]; b[2*p][1] = r[1];
            b[2*p+1][0] = r[2]; b[2*p+1][1] = r[3];
        }
#pragma unroll
        for (int t = 0; t < 2; t++)
#pragma unroll
            for (int j = 0; j < 8; j++)
                mma16816(acc[t][j], a[t], b[j]);
    }
}

// ---------------- conversions (x and W1 in one launch) -----------------------
__global__ void k_cvt2(const float* __restrict__ x, const float* __restrict__ w1,
                       __nv_bfloat16* __restrict__ xb, __nv_bfloat16* __restrict__ w1b) {
    int i = blockIdx.x * 256 + threadIdx.x;
    const int NX = NN * FIN;
    if (i < NX) xb[i] = __float2bfloat16(x[i]);
    else {
        int j = i - NX;
        if (j < NHD * FIN * FHID) w1b[j] = __float2bfloat16(w1[j]);
    }
}

// ---------------- adjacency bit-pack ----------------------------------------
__global__ void k_pack(const int* __restrict__ adj) {
    int w = blockIdx.x * 8 + (threadIdx.x >> 5);
    int lane = threadIdx.x & 31;
    int v = adj[(size_t)w * 32 + lane];
    unsigned m = __ballot_sync(0xffffffffu, v != 0);
    if (lane == 0) g_adjbits[w] = m;
}

// ---------------- K1: h1 = xb @ W1b[h]  + fused e-dot partials --------------
__global__ __launch_bounds__(256, 2) void k1_mma(const float* __restrict__ a1) {
    const int h  = blockIdx.z;
    const int bm = blockIdx.x * 128;
    const int bn = blockIdx.y * 128;
    const __nv_bfloat16* A  = g_xb;
    const __nv_bfloat16* Bp = g_W1b + (size_t)h * FIN * FHID;

    __shared__ __nv_bfloat16 As[2][128 * 40];
    __shared__ __nv_bfloat16 Bs[2][32 * 136];
    __shared__ float sa_s[128], sa_d[128];

    const int tid = threadIdx.x;
    const int warp = tid >> 5, lane = tid & 31;
    const int wm = warp & 3, wn = warp >> 2;

    float acc[2][8][4];
#pragma unroll
    for (int t = 0; t < 2; t++)
#pragma unroll
        for (int j = 0; j < 8; j++)
#pragma unroll
            for (int i = 0; i < 4; i++) acc[t][j][i] = 0.0f;

    auto loadA = [&](int buf, int k0) {
#pragma unroll
        for (int c0 = 0; c0 < 2; c0++) {
            int c = tid + c0 * 256;
            int row = c >> 2, cc = c & 3;
            cpa16(&As[buf][row * 40 + cc * 8],
                  &A[(size_t)(bm + row) * FIN + k0 + cc * 8]);
        }
    };
    auto loadB = [&](int buf, int k0) {
#pragma unroll
        for (int c0 = 0; c0 < 2; c0++) {
            int c = tid + c0 * 256;
            int br = c >> 4, bc = c & 15;
            cpa16(&Bs[buf][br * 136 + bc * 8],
                  &Bp[(size_t)(k0 + br) * FHID + bn + bc * 8]);
        }
    };

    loadA(0, 0); loadB(0, 0);
    CP_COMMIT;
    if (tid < 128) {
        sa_s[tid] = a1[h * 2 * FHID + bn + tid];
        sa_d[tid] = a1[h * 2 * FHID + FHID + bn + tid];
    }
    CP_WAIT0; __syncthreads();

    const int S = FIN / 32;   // 16
    for (int k = 0; k < S; k++) {
        int cur = k & 1, nxt = cur ^ 1;
        if (k + 1 < S) {
            loadA(nxt, (k + 1) * 32);
            loadB(nxt, (k + 1) * 32);
            CP_COMMIT;
        }
        mma_step(As[cur], Bs[cur], wm, wn, lane, acc);
        CP_WAIT0; __syncthreads();
    }

    // ---- store bf16 h1 ----
    __nv_bfloat16* Cb = g_h1b + (size_t)h * NN * FHID;
#pragma unroll
    for (int t = 0; t < 2; t++) {
        int r0 = bm + wm * 32 + t * 16 + (lane >> 2);
#pragma unroll
        for (int j = 0; j < 8; j++) {
            int col = bn + wn * 64 + j * 8 + (lane & 3) * 2;
            __nv_bfloat162 b0; b0.x = __float2bfloat16(acc[t][j][0]);
            b0.y = __float2bfloat16(acc[t][j][1]);
            __nv_bfloat162 b1; b1.x = __float2bfloat16(acc[t][j][2]);
            b1.y = __float2bfloat16(acc[t][j][3]);
            *(__nv_bfloat162*)&Cb[(size_t)r0 * FHID + col]       = b0;
            *(__nv_bfloat162*)&Cb[(size_t)(r0 + 8) * FHID + col] = b1;
        }
    }

    // ---- fused e-dot partials (this CTA's 128-col slice) ----
#pragma unroll
    for (int t = 0; t < 2; t++) {
        float s_lo = 0.0f, d_lo = 0.0f, s_hi = 0.0f, d_hi = 0.0f;
#pragma unroll
        for (int j = 0; j < 8; j++) {
            int c = wn * 64 + j * 8 + (lane & 3) * 2;   // local col 0..127
            float as0 = sa_s[c], as1 = sa_s[c + 1];
            float ad0 = sa_d[c], ad1 = sa_d[c + 1];
            s_lo += acc[t][j][0] * as0 + acc[t][j][1] * as1;
            d_lo += acc[t][j][0] * ad0 + acc[t][j][1] * ad1;
            s_hi += acc[t][j][2] * as0 + acc[t][j][3] * as1;
            d_hi += acc[t][j][2] * ad0 + acc[t][j][3] * ad1;
        }
#pragma unroll
        for (int off = 1; off <= 2; off <<= 1) {
            s_lo += __shfl_xor_sync(0xffffffffu, s_lo, off);
            d_lo += __shfl_xor_sync(0xffffffffu, d_lo, off);
            s_hi += __shfl_xor_sync(0xffffffffu, s_hi, off);
            d_hi += __shfl_xor_sync(0xffffffffu, d_hi, off);
        }
        if ((lane & 3) == 0) {
            int r0 = bm + wm * 32 + t * 16 + (lane >> 2);
            atomicAdd(&g_esrc1[h*NN + r0],     s_lo);
            atomicAdd(&g_edst1[h*NN + r0],     d_lo);
            atomicAdd(&g_esrc1[h*NN + r0 + 8], s_hi);
            atomicAdd(&g_edst1[h*NN + r0 + 8], d_hi);
        }
    }
}

// ---------------- exp decomposition prep (bf16 tables for layer 1) ----------
__global__ __launch_bounds__(256) void k_prep(int layer) {
    const float *es, *ed;
    int h = blockIdx.x;
    if (layer == 0) { es = g_esrc1 + h*NN; ed = g_edst1 + h*NN; }
    else            { es = g_esrc2;        ed = g_edst2; }
    __shared__ float red[8];
    const int tid = threadIdx.x, lane = tid & 31, wid = tid >> 5;
    float mx = -3.4e38f;
    for (int m = tid; m < NN; m += 256) mx = fmaxf(mx, ed[m]);
#pragma unroll
    for (int off = 16; off; off >>= 1) mx = fmaxf(mx, __shfl_xor_sync(0xffffffffu, mx, off));
    if (lane == 0) red[wid] = mx;
    __syncthreads();
    float maxed = red[0];
#pragma unroll
    for (int w = 1; w < 8; w++) maxed = fmaxf(maxed, red[w]);

    for (int i = tid; i < NN; i += 256) {
        float e = es[i];
        float se = e + maxed;
        float rm = se >= 0.0f ? se : 0.2f * se;
        float a1 = __expf(e - rm);
        float a2 = __expf(0.2f * e - rm);
        float d = ed[i];
        float b1 = __expf(d);
        float b2 = __expf(0.2f * d);
        if (layer == 0) {
            g_A11[h*NN + i] = a1; g_A21[h*NN + i] = a2;
            g_edB[h*NN + i] = __float2bfloat16(d);
            g_B12B[h*NN + i] = __floats2bfloat162_rn(b1, b2);
        } else {
            g_A12[i] = a1; g_A22[i] = a2;
            g_B12[i] = b1; g_B22[i] = b2;
        }
    }
}

// ---------------- fused attention GEMM (BM=128, BN=128, BK=64, 2 CTA/SM) ----
// Loop order: loadB(next) -> mma(cur) -> gen(next) -> wait -> sync.
// Tensor pipe is fed immediately after each sync; gen overlaps HMMA drain.
// SMEM (dynamic): As 2x128x72 @0 (36864B), Bs 2x64x136 @36864 (34816B),
//                 s_ed @71680 (8192B), s_b12 @79872 (16384B)
#define ATTN_SMEM 96256

__global__ __launch_bounds__(256, 2) void k_attn_fused() {
    extern __shared__ char dsm[];
    __nv_bfloat16*  As    = (__nv_bfloat16*)dsm;
    __nv_bfloat16*  Bs    = (__nv_bfloat16*)(dsm + 36864);
    __nv_bfloat16*  s_ed  = (__nv_bfloat16*)(dsm + 71680);
    __nv_bfloat162* s_b12 = (__nv_bfloat162*)(dsm + 79872);

    __shared__ float s_zp[256];
    __shared__ float s_zi[128];

    const int h  = blockIdx.z;
    const int bm = blockIdx.x * 128;
    const int bn = blockIdx.y * 128;

    const int tid  = threadIdx.x;
    const int warp = tid >> 5, lane = tid & 31;
    const int wm = warp & 3, wn = warp >> 2;
    const int row = tid >> 1, half = tid & 1;   // gen: 2 threads/row, 32 cols each

    const float es  = g_esrc1[h*NN + bm + row];
    const float a1v = g_A11 [h*NN + bm + row];
    const float a2v = g_A21 [h*NN + bm + row];
    const unsigned* ab = g_adjbits + (size_t)(bm + row) * (NN/32) + half;
    const __nv_bfloat16* Bp = g_h1b + (size_t)h * NN * FHID;

    float acc[2][8][4];
#pragma unroll
    for (int t = 0; t < 2; t++)
#pragma unroll
        for (int j = 0; j < 8; j++)
#pragma unroll
            for (int i = 0; i < 4; i++) acc[t][j][i] = 0.0f;
    float zacc = 0.0f;

    auto loadB = [&](int buf, int k0) {
        __nv_bfloat16* Bb = Bs + buf * (64 * 136);
#pragma unroll
        for (int c0 = 0; c0 < 4; c0++) {
            int c = tid + c0 * 256;
            int br = c >> 4, bc = c & 15;
            cpa16(&Bb[br * 136 + bc * 8],
                  &Bp[(size_t)(k0 + br) * FHID + bn + bc * 8]);
        }
    };

    auto gen = [&](int buf, int step, unsigned aw) {
        __nv_bfloat16* Ab = As + buf * (128 * 72);
        const int mb = step * 64 + half * 32;
#pragma unroll
        for (int g8 = 0; g8 < 4; g8++) {
            __nv_bfloat162 q[4];
#pragma unroll
            for (int jj = 0; jj < 4; jj++) {
                float p[2];
#pragma unroll
                for (int u = 0; u < 2; u++) {
                    int j = g8 * 8 + jj * 2 + u;
                    float ed = __bfloat162float(s_ed[mb + j]);
                    __nv_bfloat162 b = s_b12[mb + j];
                    float s = es + ed;
                    float v = (s >= 0.0f) ? a1v * __bfloat162float(b.x)
                                          : a2v * __bfloat162float(b.y);
                    v = ((aw >> j) & 1u) ? v : 0.0f;
                    p[u] = v; zacc += v;
                }
                q[jj] = __floats2bfloat162_rn(p[0], p[1]);
            }
            *(uint4*)&Ab[row * 72 + half * 32 + g8 * 8] = *(uint4*)q;
        }
    };

    const int S = NN / 64;   // 64 steps

    // ---- prologue ----
    loadB(0, 0); CP_COMMIT;
    {
        const uint4* es4 = (const uint4*)(g_edB  + h*NN);
        const uint4* bs4 = (const uint4*)(g_B12B + h*NN);
#pragma unroll
        for (int q = 0; q < 2; q++) ((uint4*)s_ed)[tid + q*256] = es4[tid + q*256];
#pragma unroll
        for (int q = 0; q < 4; q++) ((uint4*)s_b12)[tid + q*256] = bs4[tid + q*256];
    }
    __syncthreads();                   // tables visible
    unsigned aw_nxt = ab[2];           // word for step 1
    gen(0, 0, ab[0]);
    CP_WAIT0; __syncthreads();         // Bs[0] + As[0] ready

    for (int k = 0; k < S; k++) {
        int cur = k & 1, nxt = cur ^ 1;
        unsigned aw_n2 = (k + 2 < S) ? ab[2 * (k + 2)] : 0u;   // LDG early
        if (k + 1 < S) { loadB(nxt, (k + 1) * 64); CP_COMMIT; }
        mma_step64(As + cur * (128 * 72), Bs + cur * (64 * 136), wm, wn, lane, acc);
        if (k + 1 < S) gen(nxt, k + 1, aw_nxt);
        aw_nxt = aw_n2;
        CP_WAIT0; __syncthreads();
    }

    // ---- Z reduction (2 threads per row) ----
    s_zp[tid] = zacc;
    __syncthreads();
    if (tid < 128) s_zi[tid] = 1.0f / (s_zp[2*tid] + s_zp[2*tid + 1]);
    __syncthreads();

    // ---- epilogue: normalized bf16 out1 ----
    __nv_bfloat16* Cb = g_out1b + (size_t)h * NN * FHID;
#pragma unroll
    for (int t = 0; t < 2; t++) {
        int lr0 = wm * 32 + t * 16 + (lane >> 2);
        float iz0 = s_zi[lr0], iz1 = s_zi[lr0 + 8];
        int r0 = bm + lr0;
#pragma unroll
        for (int j = 0; j < 8; j++) {
            int col = bn + wn * 64 + j * 8 + (lane & 3) * 2;
            *(__nv_bfloat162*)&Cb[(size_t)r0 * FHID + col] =
                __floats2bfloat162_rn(acc[t][j][0] * iz0, acc[t][j][1] * iz0);
            *(__nv_bfloat162*)&Cb[(size_t)(r0 + 8) * FHID + col] =
                __floats2bfloat162_rn(acc[t][j][2] * iz1, acc[t][j][3] * iz1);
        }
    }
}

// ---------------- layer 2: fused mean/relu + feature GEMM + e2 dots ---------
__global__ __launch_bounds__(256) void k5_fused(const float* __restrict__ W2,
                                                const float* __restrict__ a2) {
    __shared__ float sW[FHID * FCLS];
    __shared__ float sH[16][FHID + 4];
    const int tid = threadIdx.x;
    const int n0 = blockIdx.x * 16;

    for (int i = tid; i < FHID * FCLS; i += 256) sW[i] = W2[i];

    {
        const int r  = tid >> 4;
        const int fb = (tid & 15) * 16;
        const int n  = n0 + r;
        float acc[16];
#pragma unroll
        for (int i = 0; i < 16; i++) acc[i] = 0.0f;
#pragma unroll
        for (int hh = 0; hh < NHD; hh++) {
            const __nv_bfloat162* src = (const __nv_bfloat162*)
                (g_out1b + ((size_t)(hh * NN + n)) * FHID + fb);
#pragma unroll
            for (int i = 0; i < 8; i++) {
                __nv_bfloat162 v = src[i];
                acc[2*i]     += __bfloat162float(v.x);
                acc[2*i + 1] += __bfloat162float(v.y);
            }
        }
#pragma unroll
        for (int i = 0; i < 16; i++) {
            float v = 0.25f * acc[i];
            sH[r][fb + i] = v > 0.0f ? v : 0.0f;
        }
    }
    __syncthreads();

    const int r = tid >> 4;
    const int o = tid & 15;
    const int n = n0 + r;
    float v = 0.0f;
#pragma unroll 8
    for (int f = 0; f < FHID; f++) v += sH[r][f] * sW[f * FCLS + o];
    g_h2[n * FCLS + o] = v;
    float vs = v * a2[o];
    float vd = v * a2[FCLS + o];
#pragma unroll
    for (int off = 8; off; off >>= 1) {
        vs += __shfl_xor_sync(0xffffffffu, vs, off);
        vd += __shfl_xor_sync(0xffffffffu, vd, off);
    }
    if (o == 0) { g_esrc2[n] = vs; g_edst2[n] = vd; }
}

// ---------------- layer 2 fused attention + log_softmax (32 rows/block) -----
__global__ __launch_bounds__(256) void k7_fused(float* __restrict__ out) {
    const int n0 = blockIdx.x * 32;
    __shared__ float sh2[512 * 17];
    __shared__ float sed[512], sb1[512], sb2[512];
    __shared__ unsigned sbits[32][16];
    __shared__ float ses[32], sA1[32], sA2[32];
    const int tid = threadIdx.x;
    const int g = tid >> 4, l = tid & 15;
    if (tid < 32) {
        ses[tid] = g_esrc2[n0 + tid];
        sA1[tid] = g_A12[n0 + tid];
        sA2[tid] = g_A22[n0 + tid];
    }
    float acc[2][16];
#pragma unroll
    for (int rb = 0; rb < 2; rb++)
#pragma unroll
        for (int o = 0; o < 16; o++) acc[rb][o] = 0.0f;
    float z[2] = {0.0f, 0.0f};

    for (int mt = 0; mt < 8; mt++) {
        __syncthreads();
#pragma unroll
        for (int j = 0; j < 32; j++) {
            int idx = tid + j * 256;
            int m = idx >> 4, o = idx & 15;
            sh2[m * 17 + o] = g_h2[(size_t)(mt*512 + m) * 16 + o];
        }
#pragma unroll
        for (int j = 0; j < 2; j++) {
            int m = tid + j * 256;
            sed[m] = g_edst2[mt*512 + m];
            sb1[m] = g_B12[mt*512 + m];
            sb2[m] = g_B22[mt*512 + m];
        }
#pragma unroll
        for (int j = 0; j < 2; j++) {
            int w = tid + j * 256;
            sbits[w >> 4][w & 15] =
                g_adjbits[(size_t)(n0 + (w >> 4)) * 128 + mt*16 + (w & 15)];
        }
        __syncthreads();
#pragma unroll
        for (int rb = 0; rb < 2; rb++) {
            int rr = rb * 16 + g;
            float eg = ses[rr], a1 = sA1[rr], a2 = sA2[rr];
#pragma unroll 4
            for (int k = 0; k < 32; k++) {
                int m = l + k * 16;
                float d = sed[m];
                float s = eg + d;
                float p = (s >= 0.0f) ? a1 * sb1[m] : a2 * sb2[m];
                if (!((sbits[rr][m >> 5] >> (m & 31)) & 1)) p = 0.0f;
                z[rb] += p;
                const float* hp = &sh2[m * 17];
#pragma unroll
                for (int o = 0; o < 16; o++) acc[rb][o] += p * hp[o];
            }
        }
    }
#pragma unroll
    for (int rb = 0; rb < 2; rb++) {
#pragma unroll
        for (int off = 8; off; off >>= 1) {
            z[rb] += __shfl_xor_sync(0xffffffffu, z[rb], off);
#pragma unroll
            for (int o = 0; o < 16; o++)
                acc[rb][o] += __shfl_xor_sync(0xffffffffu, acc[rb][o], off);
        }
        if (l == 0) {
            float inv = 1.0f / z[rb];
            float t[16], mx = -3.4e38f;
#pragma unroll
            for (int o = 0; o < 16; o++) { t[o] = acc[rb][o] * inv; mx = fmaxf(mx, t[o]); }
            float se = 0.0f;
#pragma unroll
            for (int o = 0; o < 16; o++) se += __expf(t[o] - mx);
            float lg = mx + __logf(se);
            int nrow = n0 + rb * 16 + g;
#pragma unroll
            for (int o = 0; o < 16; o++)
                out[(size_t)nrow * 16 + o] = t[o] - lg;
        }
    }
}

// ---------------------------------------------------------------------------
extern "C" void kernel_launch(void* const* d_in, const int* in_sizes, int n_in,
                              void* d_out, int out_size) {
    const float* x   = (const float*)d_in[0];
    const int*   adj = (const int*)  d_in[1];
    const float* W1  = (const float*)d_in[2];
    const float* a1  = (const float*)d_in[3];
    const float* W2  = (const float*)d_in[4];
    const float* a2  = (const float*)d_in[5];
    float* out = (float*)d_out;

    cudaFuncSetAttribute(k_attn_fused, cudaFuncAttributeMaxDynamicSharedMemorySize,
                         ATTN_SMEM);

    __nv_bfloat16* xb;  cudaGetSymbolAddress((void**)&xb,  g_xb);
    __nv_bfloat16* w1b; cudaGetSymbolAddress((void**)&w1b, g_W1b);
    float* esrc1p; cudaGetSymbolAddress((void**)&esrc1p, g_esrc1);
    float* edst1p; cudaGetSymbolAddress((void**)&edst1p, g_edst1);

    // zero e accumulators (k1 atomically accumulates into them)
    cudaMemsetAsync(esrc1p, 0, NHD * NN * sizeof(float));
    cudaMemsetAsync(edst1p, 0, NHD * NN * sizeof(float));

    const int NCVT = NN*FIN + NHD*FIN*FHID;
    k_cvt2<<<(NCVT + 255)/256, 256>>>(x, W1, xb, w1b);
    k_pack<<<(NN*NN/32)/8, 256>>>(adj);

    // layer 1
    dim3 gg(NN/128, FHID/128, NHD);              // 32 x 2 x 4 = 256 CTAs
    k1_mma<<<gg, 256>>>(a1);                     // h1 (bf16) + e-dot atomics
    k_prep<<<NHD, 256>>>(0);
    dim3 ga(NN/128, FHID/128, NHD);              // 32 x 2 x 4 = 256 CTAs
    k_attn_fused<<<ga, 256, ATTN_SMEM>>>();

    // layer 2
    k5_fused<<<NN/16, 256>>>(W2, a2);
    k_prep<<<1, 256>>>(1);
    k7_fused<<<NN/32, 256>>>(out);
}

// round 16
// speedup vs baseline: 1.0660x; 1.0660x over previous
#include <cuda_runtime.h>
#include <cuda_bf16.h>
#include <cstdint>

#define NN    4096
#define FIN   512
#define FHID  256
#define FCLS  16
#define NHD   4

// ---------------- scratch (static device globals) ---------------------------
__device__ __nv_bfloat16  g_h1b  [NHD*NN*FHID];        // 8 MB
__device__ __nv_bfloat16  g_out1b[NHD*NN*FHID];        // 8 MB
__device__ __nv_bfloat16  g_xb  [NN*FIN];              // 4 MB
__device__ __nv_bfloat16  g_W1b [NHD*FIN*FHID];        // 1 MB
__device__ unsigned       g_adjbits[(size_t)NN*NN/32]; // 2 MB
__device__ __nv_bfloat16  g_edB [NHD*NN];              // rank-1 tables (bf16)
__device__ __nv_bfloat162 g_B12B[NHD*NN];
__device__ float g_esrc1[NHD*NN], g_edst1[NHD*NN];
__device__ float g_A11[NHD*NN], g_A21[NHD*NN];
__device__ float g_h2[NN*FCLS];
__device__ float g_esrc2[NN], g_edst2[NN];
__device__ float g_A12[NN], g_A22[NN], g_B12[NN], g_B22[NN];

// ---------------- PTX helpers ------------------------------------------------
__device__ __forceinline__ uint32_t smem_u32(const void* p) {
    uint32_t a;
    asm("{ .reg .u64 t; cvta.to.shared.u64 t, %1; cvt.u32.u64 %0, t; }"
        : "=r"(a) : "l"(p));
    return a;
}
__device__ __forceinline__ void mma16816(float* c, const uint32_t* a, const uint32_t* b) {
    asm volatile("mma.sync.aligned.m16n8k16.row.col.f32.bf16.bf16.f32 "
                 "{%0,%1,%2,%3}, {%4,%5,%6,%7}, {%8,%9}, {%0,%1,%2,%3};\n"
                 : "+f"(c[0]), "+f"(c[1]), "+f"(c[2]), "+f"(c[3])
                 : "r"(a[0]), "r"(a[1]), "r"(a[2]), "r"(a[3]),
                   "r"(b[0]), "r"(b[1]));
}
__device__ __forceinline__ void ldsm_x4(uint32_t* r, const void* p) {
    uint32_t a = smem_u32(p);
    asm volatile("ldmatrix.sync.aligned.m8n8.x4.shared.b16 {%0,%1,%2,%3}, [%4];"
                 : "=r"(r[0]), "=r"(r[1]), "=r"(r[2]), "=r"(r[3]) : "r"(a));
}
__device__ __forceinline__ void ldsm_x4_t(uint32_t* r, const void* p) {
    uint32_t a = smem_u32(p);
    asm volatile("ldmatrix.sync.aligned.m8n8.x4.trans.shared.b16 {%0,%1,%2,%3}, [%4];"
                 : "=r"(r[0]), "=r"(r[1]), "=r"(r[2]), "=r"(r[3]) : "r"(a));
}
__device__ __forceinline__ void cpa16(void* s, const void* g) {
    uint32_t sa = smem_u32(s);
    asm volatile("cp.async.cg.shared.global [%0], [%1], 16;\n" :: "r"(sa), "l"(g));
}
#define CP_COMMIT asm volatile("cp.async.commit_group;\n" ::: "memory")
#define CP_WAIT0  asm volatile("cp.async.wait_group 0;\n" ::: "memory")

// ---------------- k1 mma micro-kernel (128x128, 4x2 warps, BK=32) -----------
__device__ __forceinline__ void mma_step(const __nv_bfloat16* As, const __nv_bfloat16* Bs,
                                         int wm, int wn, int lane, float acc[2][8][4]) {
#pragma unroll
    for (int s = 0; s < 2; s++) {
        uint32_t a[2][4];
        const int lr = lane & 15, lc = lane >> 4;
#pragma unroll
        for (int t = 0; t < 2; t++)
            ldsm_x4(a[t], &As[(wm * 32 + t * 16 + lr) * 40 + s * 16 + lc * 8]);
        uint32_t b[8][2];
        const int brow = s * 16 + (lane & 7) + (lane & 8);
        const int bco  = (lane & 16) >> 1;
#pragma unroll
        for (int p = 0; p < 4; p++) {
            uint32_t r[4];
            ldsm_x4_t(r, &Bs[brow * 136 + wn * 64 + p * 16 + bco]);
            b[2*p][0] = r[0]; b[2*p][1] = r[1];
            b[2*p+1][0] = r[2]; b[2*p+1][1] = r[3];
        }
#pragma unroll
        for (int t = 0; t < 2; t++)
#pragma unroll
            for (int j = 0; j < 8; j++)
                mma16816(acc[t][j], a[t], b[j]);
    }
}

// ---------------- attention mma micro-kernel (128x128, 4x2 warps, BK=64) ----
__device__ __forceinline__ void mma_step64(const __nv_bfloat16* As, const __nv_bfloat16* Bs,
                                           int wm, int wn, int lane, float acc[2][8][4]) {
#pragma unroll
    for (int s = 0; s < 4; s++) {
        uint32_t a[2][4];
        const int lr = lane & 15, lc = lane >> 4;
#pragma unroll
        for (int t = 0; t < 2; t++)
            ldsm_x4(a[t], &As[(wm * 32 + t * 16 + lr) * 72 + s * 16 + lc * 8]);
        uint32_t b[8][2];
        const int brow = s * 16 + (lane & 7) + (lane & 8);
        const int bco  = (lane & 16) >> 1;
#pragma unroll
        for (int p = 0; p < 4; p++) {
            uint32_t r[4];
            ldsm_x4_t(r, &Bs[brow * 136 + wn * 64 + p * 16 + bco]);
            b[2*p][0] = r[0]; b[2*p][1] = r[1];
            b[2*p+1][0] = r[2]; b[2*p+1][1] = r[3];
        }
#pragma unroll
        for (int t = 0; t < 2; t++)
#pragma unroll
            for (int j = 0; j < 8; j++)
                mma16816(acc[t][j], a[t], b[j]);
    }
}

// ---------------- conversions (x and W1 in one launch) -----------------------
__global__ void k_cvt2(const float* __restrict__ x, const float* __restrict__ w1,
                       __nv_bfloat16* __restrict__ xb, __nv_bfloat16* __restrict__ w1b) {
    int i = blockIdx.x * 256 + threadIdx.x;
    const int NX = NN * FIN;
    if (i < NX) xb[i] = __float2bfloat16(x[i]);
    else {
        int j = i - NX;
        if (j < NHD * FIN * FHID) w1b[j] = __float2bfloat16(w1[j]);
    }
}

// ---------------- adjacency bit-pack ----------------------------------------
__global__ void k_pack(const int* __restrict__ adj) {
    int w = blockIdx.x * 8 + (threadIdx.x >> 5);
    int lane = threadIdx.x & 31;
    int v = adj[(size_t)w * 32 + lane];
    unsigned m = __ballot_sync(0xffffffffu, v != 0);
    if (lane == 0) g_adjbits[w] = m;
}

// ---------------- K1: h1 = xb @ W1b[h] (at HMMA floor) ----------------------
__global__ __launch_bounds__(256, 2) void k1_mma() {
    const int h  = blockIdx.z;
    const int bm = blockIdx.x * 128;
    const int bn = blockIdx.y * 128;
    const __nv_bfloat16* A  = g_xb;
    const __nv_bfloat16* Bp = g_W1b + (size_t)h * FIN * FHID;

    __shared__ __nv_bfloat16 As[2][128 * 40];
    __shared__ __nv_bfloat16 Bs[2][32 * 136];

    const int tid = threadIdx.x;
    const int warp = tid >> 5, lane = tid & 31;
    const int wm = warp & 3, wn = warp >> 2;

    float acc[2][8][4];
#pragma unroll
    for (int t = 0; t < 2; t++)
#pragma unroll
        for (int j = 0; j < 8; j++)
#pragma unroll
            for (int i = 0; i < 4; i++) acc[t][j][i] = 0.0f;

    auto loadA = [&](int buf, int k0) {
#pragma unroll
        for (int c0 = 0; c0 < 2; c0++) {
            int c = tid + c0 * 256;
            int row = c >> 2, cc = c & 3;
            cpa16(&As[buf][row * 40 + cc * 8],
                  &A[(size_t)(bm + row) * FIN + k0 + cc * 8]);
        }
    };
    auto loadB = [&](int buf, int k0) {
#pragma unroll
        for (int c0 = 0; c0 < 2; c0++) {
            int c = tid + c0 * 256;
            int br = c >> 4, bc = c & 15;
            cpa16(&Bs[buf][br * 136 + bc * 8],
                  &Bp[(size_t)(k0 + br) * FHID + bn + bc * 8]);
        }
    };

    loadA(0, 0); loadB(0, 0);
    CP_COMMIT; CP_WAIT0; __syncthreads();

    const int S = FIN / 32;   // 16
    for (int k = 0; k < S; k++) {
        int cur = k & 1, nxt = cur ^ 1;
        if (k + 1 < S) {
            loadA(nxt, (k + 1) * 32);
            loadB(nxt, (k + 1) * 32);
            CP_COMMIT;
        }
        mma_step(As[cur], Bs[cur], wm, wn, lane, acc);
        CP_WAIT0; __syncthreads();
    }

    __nv_bfloat16* Cb = g_h1b + (size_t)h * NN * FHID;
#pragma unroll
    for (int t = 0; t < 2; t++) {
        int r0 = bm + wm * 32 + t * 16 + (lane >> 2);
#pragma unroll
        for (int j = 0; j < 8; j++) {
            int col = bn + wn * 64 + j * 8 + (lane & 3) * 2;
            __nv_bfloat162 b0; b0.x = __float2bfloat16(acc[t][j][0]);
            b0.y = __float2bfloat16(acc[t][j][1]);
            __nv_bfloat162 b1; b1.x = __float2bfloat16(acc[t][j][2]);
            b1.y = __float2bfloat16(acc[t][j][3]);
            *(__nv_bfloat162*)&Cb[(size_t)r0 * FHID + col]       = b0;
            *(__nv_bfloat162*)&Cb[(size_t)(r0 + 8) * FHID + col] = b1;
        }
    }
}

// ---------------- e_src/e_dst dot products (bf16 h1) ------------------------
__global__ __launch_bounds__(256) void k_edot(const float* __restrict__ a1) {
    const int w    = (blockIdx.x * blockDim.x + threadIdx.x) >> 5;
    const int lane = threadIdx.x & 31;
    const int h = w >> 12;
    const int n = w & (NN - 1);
    const __nv_bfloat16* hrow = g_h1b + ((size_t)h * NN + n) * FHID;
    const float* asrc = a1 + h * 2 * FHID;
    const float* adst = asrc + FHID;
    float s = 0.0f, d = 0.0f;
#pragma unroll
    for (int o = lane; o < FHID; o += 32) {
        float v = __bfloat162float(hrow[o]);
        s += v * asrc[o];
        d += v * adst[o];
    }
#pragma unroll
    for (int off = 16; off; off >>= 1) {
        s += __shfl_xor_sync(0xffffffffu, s, off);
        d += __shfl_xor_sync(0xffffffffu, d, off);
    }
    if (lane == 0) { g_esrc1[h*NN + n] = s; g_edst1[h*NN + n] = d; }
}

// ---------------- exp decomposition prep (PARALLEL: 16 blocks per head) -----
// Each block redundantly max-reduces the full ed array (L2-resident), then
// generates its own 256-element slice (1 element/thread).
__global__ __launch_bounds__(256) void k_prep(int layer) {
    const int h     = (layer == 0) ? (blockIdx.x >> 4) : 0;
    const int slice = blockIdx.x & 15;
    const float *es, *ed;
    if (layer == 0) { es = g_esrc1 + h*NN; ed = g_edst1 + h*NN; }
    else            { es = g_esrc2;        ed = g_edst2; }

    __shared__ float red[8];
    const int tid = threadIdx.x, lane = tid & 31, wid = tid >> 5;
    float mx = -3.4e38f;
    const float4* ed4 = (const float4*)ed;
#pragma unroll 4
    for (int m = tid; m < NN/4; m += 256) {
        float4 v = ed4[m];
        mx = fmaxf(mx, fmaxf(fmaxf(v.x, v.y), fmaxf(v.z, v.w)));
    }
#pragma unroll
    for (int off = 16; off; off >>= 1) mx = fmaxf(mx, __shfl_xor_sync(0xffffffffu, mx, off));
    if (lane == 0) red[wid] = mx;
    __syncthreads();
    float maxed = red[0];
#pragma unroll
    for (int w = 1; w < 8; w++) maxed = fmaxf(maxed, red[w]);

    const int i = slice * 256 + tid;
    float e = es[i];
    float se = e + maxed;
    float rm = se >= 0.0f ? se : 0.2f * se;
    float a1 = __expf(e - rm);
    float a2 = __expf(0.2f * e - rm);
    float d = ed[i];
    float b1 = __expf(d);
    float b2 = __expf(0.2f * d);
    if (layer == 0) {
        g_A11[h*NN + i] = a1; g_A21[h*NN + i] = a2;
        g_edB[h*NN + i] = __float2bfloat16(d);
        g_B12B[h*NN + i] = __floats2bfloat162_rn(b1, b2);
    } else {
        g_A12[i] = a1; g_A22[i] = a2;
        g_B12[i] = b1; g_B22[i] = b2;
    }
}

// ---------------- fused attention GEMM (BM=128, BN=128, BK=64, 2 CTA/SM) ----
// SMEM (dynamic): As 2x128x72 @0 (36864B), Bs 2x64x136 @36864 (34816B),
//                 s_ed @71680 (8192B), s_b12 @79872 (16384B)
#define ATTN_SMEM 96256

__global__ __launch_bounds__(256, 2) void k_attn_fused() {
    extern __shared__ char dsm[];
    __nv_bfloat16*  As    = (__nv_bfloat16*)dsm;
    __nv_bfloat16*  Bs    = (__nv_bfloat16*)(dsm + 36864);
    __nv_bfloat16*  s_ed  = (__nv_bfloat16*)(dsm + 71680);
    __nv_bfloat162* s_b12 = (__nv_bfloat162*)(dsm + 79872);

    __shared__ float s_zp[256];
    __shared__ float s_zi[128];

    const int h  = blockIdx.z;
    const int bm = blockIdx.x * 128;
    const int bn = blockIdx.y * 128;

    const int tid  = threadIdx.x;
    const int warp = tid >> 5, lane = tid & 31;
    const int wm = warp & 3, wn = warp >> 2;
    const int row = tid >> 1, half = tid & 1;   // gen: 2 threads/row, 32 cols each

    const float es  = g_esrc1[h*NN + bm + row];
    const float a1v = g_A11 [h*NN + bm + row];
    const float a2v = g_A21 [h*NN + bm + row];
    const unsigned* ab = g_adjbits + (size_t)(bm + row) * (NN/32) + half;
    const __nv_bfloat16* Bp = g_h1b + (size_t)h * NN * FHID;

    float acc[2][8][4];
#pragma unroll
    for (int t = 0; t < 2; t++)
#pragma unroll
        for (int j = 0; j < 8; j++)
#pragma unroll
            for (int i = 0; i < 4; i++) acc[t][j][i] = 0.0f;
    float zacc = 0.0f;

    auto loadB = [&](int buf, int k0) {
        __nv_bfloat16* Bb = Bs + buf * (64 * 136);
#pragma unroll
        for (int c0 = 0; c0 < 4; c0++) {
            int c = tid + c0 * 256;
            int br = c >> 4, bc = c & 15;
            cpa16(&Bb[br * 136 + bc * 8],
                  &Bp[(size_t)(k0 + br) * FHID + bn + bc * 8]);
        }
    };

    auto gen = [&](int buf, int step, unsigned aw) {
        __nv_bfloat16* Ab = As + buf * (128 * 72);
        const int mb = step * 64 + half * 32;
#pragma unroll
        for (int g8 = 0; g8 < 4; g8++) {
            __nv_bfloat162 q[4];
#pragma unroll
            for (int jj = 0; jj < 4; jj++) {
                float p[2];
#pragma unroll
                for (int u = 0; u < 2; u++) {
                    int j = g8 * 8 + jj * 2 + u;
                    float ed = __bfloat162float(s_ed[mb + j]);
                    __nv_bfloat162 b = s_b12[mb + j];
                    float s = es + ed;
                    float v = (s >= 0.0f) ? a1v * __bfloat162float(b.x)
                                          : a2v * __bfloat162float(b.y);
                    v = ((aw >> j) & 1u) ? v : 0.0f;
                    p[u] = v; zacc += v;
                }
                q[jj] = __floats2bfloat162_rn(p[0], p[1]);
            }
            *(uint4*)&Ab[row * 72 + half * 32 + g8 * 8] = *(uint4*)q;
        }
    };

    const int S = NN / 64;   // 64 steps

    // ---- prologue ----
    loadB(0, 0); CP_COMMIT;
    {
        const uint4* es4 = (const uint4*)(g_edB  + h*NN);
        const uint4* bs4 = (const uint4*)(g_B12B + h*NN);
#pragma unroll
        for (int q = 0; q < 2; q++) ((uint4*)s_ed)[tid + q*256] = es4[tid + q*256];
#pragma unroll
        for (int q = 0; q < 4; q++) ((uint4*)s_b12)[tid + q*256] = bs4[tid + q*256];
    }
    __syncthreads();                   // tables visible
    unsigned aw_nxt = ab[2];           // word for step 1
    gen(0, 0, ab[0]);
    CP_WAIT0; __syncthreads();         // Bs[0] + As[0] ready

    for (int k = 0; k < S; k++) {
        int cur = k & 1, nxt = cur ^ 1;
        if (k + 1 < S) {
            loadB(nxt, (k + 1) * 64);
            CP_COMMIT;
            gen(nxt, k + 1, aw_nxt);
            aw_nxt = (k + 2 < S) ? ab[2 * (k + 2)] : 0u;
        }
        mma_step64(As + cur * (128 * 72), Bs + cur * (64 * 136), wm, wn, lane, acc);
        CP_WAIT0; __syncthreads();
    }

    // ---- Z reduction (2 threads per row) ----
    s_zp[tid] = zacc;
    __syncthreads();
    if (tid < 128) s_zi[tid] = 1.0f / (s_zp[2*tid] + s_zp[2*tid + 1]);
    __syncthreads();

    // ---- epilogue: normalized bf16 out1 ----
    __nv_bfloat16* Cb = g_out1b + (size_t)h * NN * FHID;
#pragma unroll
    for (int t = 0; t < 2; t++) {
        int lr0 = wm * 32 + t * 16 + (lane >> 2);
        float iz0 = s_zi[lr0], iz1 = s_zi[lr0 + 8];
        int r0 = bm + lr0;
#pragma unroll
        for (int j = 0; j < 8; j++) {
            int col = bn + wn * 64 + j * 8 + (lane & 3) * 2;
            *(__nv_bfloat162*)&Cb[(size_t)r0 * FHID + col] =
                __floats2bfloat162_rn(acc[t][j][0] * iz0, acc[t][j][1] * iz0);
            *(__nv_bfloat162*)&Cb[(size_t)(r0 + 8) * FHID + col] =
                __floats2bfloat162_rn(acc[t][j][2] * iz1, acc[t][j][3] * iz1);
        }
    }
}

// ---------------- layer 2: fused mean/relu + feature GEMM + e2 dots ---------
__global__ __launch_bounds__(256) void k5_fused(const float* __restrict__ W2,
                                                const float* __restrict__ a2) {
    __shared__ float sW[FHID * FCLS];
    __shared__ float sH[16][FHID + 4];
    const int tid = threadIdx.x;
    const int n0 = blockIdx.x * 16;

    for (int i = tid; i < FHID * FCLS; i += 256) sW[i] = W2[i];

    {
        const int r  = tid >> 4;
        const int fb = (tid & 15) * 16;
        const int n  = n0 + r;
        float acc[16];
#pragma unroll
        for (int i = 0; i < 16; i++) acc[i] = 0.0f;
#pragma unroll
        for (int hh = 0; hh < NHD; hh++) {
            const __nv_bfloat162* src = (const __nv_bfloat162*)
                (g_out1b + ((size_t)(hh * NN + n)) * FHID + fb);
#pragma unroll
            for (int i = 0; i < 8; i++) {
                __nv_bfloat162 v = src[i];
                acc[2*i]     += __bfloat162float(v.x);
                acc[2*i + 1] += __bfloat162float(v.y);
            }
        }
#pragma unroll
        for (int i = 0; i < 16; i++) {
            float v = 0.25f * acc[i];
            sH[r][fb + i] = v > 0.0f ? v : 0.0f;
        }
    }
    __syncthreads();

    const int r = tid >> 4;
    const int o = tid & 15;
    const int n = n0 + r;
    float v = 0.0f;
#pragma unroll 8
    for (int f = 0; f < FHID; f++) v += sH[r][f] * sW[f * FCLS + o];
    g_h2[n * FCLS + o] = v;
    float vs = v * a2[o];
    float vd = v * a2[FCLS + o];
#pragma unroll
    for (int off = 8; off; off >>= 1) {
        vs += __shfl_xor_sync(0xffffffffu, vs, off);
        vd += __shfl_xor_sync(0xffffffffu, vd, off);
    }
    if (o == 0) { g_esrc2[n] = vs; g_edst2[n] = vd; }
}

// ---------------- layer 2 fused attention + log_softmax ---------------------
__global__ __launch_bounds__(256) void k7_fused(float* __restrict__ out) {
    const int n0 = blockIdx.x * 16;
    __shared__ float sh2[512 * 17];
    __shared__ float sed[512], sb1[512], sb2[512];
    __shared__ unsigned sbits[16][16];
    __shared__ float ses[16], sA1[16], sA2[16];
    const int tid = threadIdx.x;
    const int g = tid >> 4, l = tid & 15;
    if (tid < 16) {
        ses[tid] = g_esrc2[n0 + tid];
        sA1[tid] = g_A12[n0 + tid];
        sA2[tid] = g_A22[n0 + tid];
    }
    float acc[16];
#pragma unroll
    for (int o = 0; o < 16; o++) acc[o] = 0.0f;
    float z = 0.0f;

    for (int mt = 0; mt < 8; mt++) {
        __syncthreads();
#pragma unroll
        for (int j = 0; j < 32; j++) {
            int idx = tid + j * 256;
            int m = idx >> 4, o = idx & 15;
            sh2[m * 17 + o] = g_h2[(size_t)(mt*512 + m) * 16 + o];
        }
#pragma unroll
        for (int j = 0; j < 2; j++) {
            int m = tid + j * 256;
            sed[m] = g_edst2[mt*512 + m];
            sb1[m] = g_B12[mt*512 + m];
            sb2[m] = g_B22[mt*512 + m];
        }
        {
            int w = tid;
            if (w < 256) sbits[w >> 4][w & 15] =
                g_adjbits[(size_t)(n0 + (w >> 4)) * 128 + mt*16 + (w & 15)];
        }
        __syncthreads();
        float eg = ses[g], a1 = sA1[g], a2 = sA2[g];
#pragma unroll 4
        for (int k = 0; k < 32; k++) {
            int m = l + k * 16;
            float d = sed[m];
            float s = eg + d;
            float p = (s >= 0.0f) ? a1 * sb1[m] : a2 * sb2[m];
            if (!((sbits[g][m >> 5] >> (m & 31)) & 1)) p = 0.0f;
            z += p;
            const float* hp = &sh2[m * 17];
#pragma unroll
            for (int o = 0; o < 16; o++) acc[o] += p * hp[o];
        }
    }
#pragma unroll
    for (int off = 8; off; off >>= 1) {
        z += __shfl_xor_sync(0xffffffffu, z, off);
#pragma unroll
        for (int o = 0; o < 16; o++)
            acc[o] += __shfl_xor_sync(0xffffffffu, acc[o], off);
    }
    if (l == 0) {
        float inv = 1.0f / z;
        float t[16], mx = -3.4e38f;
#pragma unroll
        for (int o = 0; o < 16; o++) { t[o] = acc[o] * inv; mx = fmaxf(mx, t[o]); }
        float se = 0.0f;
#pragma unroll
        for (int o = 0; o < 16; o++) se += __expf(t[o] - mx);
        float lg = mx + __logf(se);
#pragma unroll
        for (int o = 0; o < 16; o++)
            out[(size_t)(n0 + g) * 16 + o] = t[o] - lg;
    }
}

// ---------------------------------------------------------------------------
extern "C" void kernel_launch(void* const* d_in, const int* in_sizes, int n_in,
                              void* d_out, int out_size) {
    const float* x   = (const float*)d_in[0];
    const int*   adj = (const int*)  d_in[1];
    const float* W1  = (const float*)d_in[2];
    const float* a1  = (const float*)d_in[3];
    const float* W2  = (const float*)d_in[4];
    const float* a2  = (const float*)d_in[5];
    float* out = (float*)d_out;

    cudaFuncSetAttribute(k_attn_fused, cudaFuncAttributeMaxDynamicSharedMemorySize,
                         ATTN_SMEM);

    __nv_bfloat16* xb;  cudaGetSymbolAddress((void**)&xb,  g_xb);
    __nv_bfloat16* w1b; cudaGetSymbolAddress((void**)&w1b, g_W1b);

    const int NCVT = NN*FIN + NHD*FIN*FHID;
    k_cvt2<<<(NCVT + 255)/256, 256>>>(x, W1, xb, w1b);
    k_pack<<<(NN*NN/32)/8, 256>>>(adj);

    // layer 1
    dim3 gg(NN/128, FHID/128, NHD);              // 32 x 2 x 4 = 256 CTAs
    k1_mma<<<gg, 256>>>();
    k_edot<<<(NHD*NN)/8, 256>>>(a1);
    k_prep<<<NHD * 16, 256>>>(0);                // 64 blocks (parallel)
    dim3 ga(NN/128, FHID/128, NHD);              // 32 x 2 x 4 = 256 CTAs
    k_attn_fused<<<ga, 256, ATTN_SMEM>>>();

    // layer 2
    k5_fused<<<NN/16, 256>>>(W2, a2);
    k_prep<<<16, 256>>>(1);                      // 16 blocks (parallel)
    k7_fused<<<NN/16, 256>>>(out);
}

// round 17
// speedup vs baseline: 1.0929x; 1.0252x over previous
#include <cuda_runtime.h>
#include <cuda_bf16.h>
#include <cstdint>

#define NN    4096
#define FIN   512
#define FHID  256
#define FCLS  16
#define NHD   4

// ---------------- scratch (static device globals) ---------------------------
__device__ __nv_bfloat16  g_h1b  [NHD*NN*FHID];        // 8 MB
__device__ __nv_bfloat16  g_out1b[NHD*NN*FHID];        // 8 MB
__device__ __nv_bfloat16  g_xb  [NN*FIN];              // 4 MB
__device__ __nv_bfloat16  g_W1b [NHD*FIN*FHID];        // 1 MB
__device__ unsigned       g_adjbits[(size_t)NN*NN/32]; // 2 MB
__device__ uint2          g_tab [NHD*NN];              // packed (ed|b1, b2) bf16
__device__ float g_esrc1[NHD*NN], g_edst1[NHD*NN];
__device__ float g_A11[NHD*NN], g_A21[NHD*NN];
__device__ float g_h2[NN*FCLS];
__device__ float g_esrc2[NN], g_edst2[NN];
__device__ float g_A12[NN], g_A22[NN], g_B12[NN], g_B22[NN];

// ---------------- PTX helpers ------------------------------------------------
__device__ __forceinline__ uint32_t smem_u32(const void* p) {
    uint32_t a;
    asm("{ .reg .u64 t; cvta.to.shared.u64 t, %1; cvt.u32.u64 %0, t; }"
        : "=r"(a) : "l"(p));
    return a;
}
__device__ __forceinline__ void mma16816(float* c, const uint32_t* a, const uint32_t* b) {
    asm volatile("mma.sync.aligned.m16n8k16.row.col.f32.bf16.bf16.f32 "
                 "{%0,%1,%2,%3}, {%4,%5,%6,%7}, {%8,%9}, {%0,%1,%2,%3};\n"
                 : "+f"(c[0]), "+f"(c[1]), "+f"(c[2]), "+f"(c[3])
                 : "r"(a[0]), "r"(a[1]), "r"(a[2]), "r"(a[3]),
                   "r"(b[0]), "r"(b[1]));
}
__device__ __forceinline__ void ldsm_x4(uint32_t* r, const void* p) {
    uint32_t a = smem_u32(p);
    asm volatile("ldmatrix.sync.aligned.m8n8.x4.shared.b16 {%0,%1,%2,%3}, [%4];"
                 : "=r"(r[0]), "=r"(r[1]), "=r"(r[2]), "=r"(r[3]) : "r"(a));
}
__device__ __forceinline__ void ldsm_x4_t(uint32_t* r, const void* p) {
    uint32_t a = smem_u32(p);
    asm volatile("ldmatrix.sync.aligned.m8n8.x4.trans.shared.b16 {%0,%1,%2,%3}, [%4];"
                 : "=r"(r[0]), "=r"(r[1]), "=r"(r[2]), "=r"(r[3]) : "r"(a));
}
__device__ __forceinline__ void cpa16(void* s, const void* g) {
    uint32_t sa = smem_u32(s);
    asm volatile("cp.async.cg.shared.global [%0], [%1], 16;\n" :: "r"(sa), "l"(g));
}
#define CP_COMMIT asm volatile("cp.async.commit_group;\n" ::: "memory")
#define CP_WAIT0  asm volatile("cp.async.wait_group 0;\n" ::: "memory")

__device__ __forceinline__ float bf_lo(uint32_t w) {
    return __bfloat162float(__ushort_as_bfloat16((unsigned short)(w & 0xffffu)));
}
__device__ __forceinline__ float bf_hi(uint32_t w) {
    return __bfloat162float(__ushort_as_bfloat16((unsigned short)(w >> 16)));
}

// ---------------- BK=64 mma micro-kernel (128x128, 4x2 warps) ----------------
// As stride 72 (64 k + 8 pad), Bs stride 136, 64 k-rows.
__device__ __forceinline__ void mma_step64(const __nv_bfloat16* As, const __nv_bfloat16* Bs,
                                           int wm, int wn, int lane, float acc[2][8][4]) {
#pragma unroll
    for (int s = 0; s < 4; s++) {
        uint32_t a[2][4];
        const int lr = lane & 15, lc = lane >> 4;
#pragma unroll
        for (int t = 0; t < 2; t++)
            ldsm_x4(a[t], &As[(wm * 32 + t * 16 + lr) * 72 + s * 16 + lc * 8]);
        uint32_t b[8][2];
        const int brow = s * 16 + (lane & 7) + (lane & 8);
        const int bco  = (lane & 16) >> 1;
#pragma unroll
        for (int p = 0; p < 4; p++) {
            uint32_t r[4];
            ldsm_x4_t(r, &Bs[brow * 136 + wn * 64 + p * 16 + bco]);
            b[2*p][0] = r[0]; b[2*p][1] = r[1];
            b[2*p+1][0] = r[2]; b[2*p+1][1] = r[3];
        }
#pragma unroll
        for (int t = 0; t < 2; t++)
#pragma unroll
            for (int j = 0; j < 8; j++)
                mma16816(acc[t][j], a[t], b[j]);
    }
}

// ---------------- conversions (x and W1 in one launch) -----------------------
__global__ void k_cvt2(const float* __restrict__ x, const float* __restrict__ w1,
                       __nv_bfloat16* __restrict__ xb, __nv_bfloat16* __restrict__ w1b) {
    int i = blockIdx.x * 256 + threadIdx.x;
    const int NX = NN * FIN;
    if (i < NX) xb[i] = __float2bfloat16(x[i]);
    else {
        int j = i - NX;
        if (j < NHD * FIN * FHID) w1b[j] = __float2bfloat16(w1[j]);
    }
}

// ---------------- adjacency bit-pack ----------------------------------------
__global__ void k_pack(const int* __restrict__ adj) {
    int w = blockIdx.x * 8 + (threadIdx.x >> 5);
    int lane = threadIdx.x & 31;
    int v = adj[(size_t)w * 32 + lane];
    unsigned m = __ballot_sync(0xffffffffu, v != 0);
    if (lane == 0) g_adjbits[w] = m;
}

// ---------------- K1: h1 = xb @ W1b[h]  (BK=64, 8 steps) --------------------
// SMEM (dynamic): As 2x128x72 @0 (36864B), Bs 2x64x136 @36864 (34816B)
#define K1_SMEM 71680

__global__ __launch_bounds__(256, 2) void k1_mma() {
    extern __shared__ char k1sm[];
    __nv_bfloat16* As = (__nv_bfloat16*)k1sm;
    __nv_bfloat16* Bs = (__nv_bfloat16*)(k1sm + 36864);

    const int h  = blockIdx.z;
    const int bm = blockIdx.x * 128;
    const int bn = blockIdx.y * 128;
    const __nv_bfloat16* A  = g_xb;
    const __nv_bfloat16* Bp = g_W1b + (size_t)h * FIN * FHID;

    const int tid = threadIdx.x;
    const int warp = tid >> 5, lane = tid & 31;
    const int wm = warp & 3, wn = warp >> 2;

    float acc[2][8][4];
#pragma unroll
    for (int t = 0; t < 2; t++)
#pragma unroll
        for (int j = 0; j < 8; j++)
#pragma unroll
            for (int i = 0; i < 4; i++) acc[t][j][i] = 0.0f;

    auto loadA = [&](int buf, int k0) {
        __nv_bfloat16* Ab = As + buf * (128 * 72);
#pragma unroll
        for (int c0 = 0; c0 < 4; c0++) {
            int c = tid + c0 * 256;
            int row = c >> 3, cc = c & 7;
            cpa16(&Ab[row * 72 + cc * 8],
                  &A[(size_t)(bm + row) * FIN + k0 + cc * 8]);
        }
    };
    auto loadB = [&](int buf, int k0) {
        __nv_bfloat16* Bb = Bs + buf * (64 * 136);
#pragma unroll
        for (int c0 = 0; c0 < 4; c0++) {
            int c = tid + c0 * 256;
            int br = c >> 4, bc = c & 15;
            cpa16(&Bb[br * 136 + bc * 8],
                  &Bp[(size_t)(k0 + br) * FHID + bn + bc * 8]);
        }
    };

    loadA(0, 0); loadB(0, 0);
    CP_COMMIT; CP_WAIT0; __syncthreads();

    const int S = FIN / 64;   // 8
    for (int k = 0; k < S; k++) {
        int cur = k & 1, nxt = cur ^ 1;
        if (k + 1 < S) {
            loadA(nxt, (k + 1) * 64);
            loadB(nxt, (k + 1) * 64);
            CP_COMMIT;
        }
        mma_step64(As + cur * (128 * 72), Bs + cur * (64 * 136), wm, wn, lane, acc);
        CP_WAIT0; __syncthreads();
    }

    __nv_bfloat16* Cb = g_h1b + (size_t)h * NN * FHID;
#pragma unroll
    for (int t = 0; t < 2; t++) {
        int r0 = bm + wm * 32 + t * 16 + (lane >> 2);
#pragma unroll
        for (int j = 0; j < 8; j++) {
            int col = bn + wn * 64 + j * 8 + (lane & 3) * 2;
            __nv_bfloat162 b0; b0.x = __float2bfloat16(acc[t][j][0]);
            b0.y = __float2bfloat16(acc[t][j][1]);
            __nv_bfloat162 b1; b1.x = __float2bfloat16(acc[t][j][2]);
            b1.y = __float2bfloat16(acc[t][j][3]);
            *(__nv_bfloat162*)&Cb[(size_t)r0 * FHID + col]       = b0;
            *(__nv_bfloat162*)&Cb[(size_t)(r0 + 8) * FHID + col] = b1;
        }
    }
}

// ---------------- e_src/e_dst dot products (bf16 h1) ------------------------
__global__ __launch_bounds__(256) void k_edot(const float* __restrict__ a1) {
    const int w    = (blockIdx.x * blockDim.x + threadIdx.x) >> 5;
    const int lane = threadIdx.x & 31;
    const int h = w >> 12;
    const int n = w & (NN - 1);
    const __nv_bfloat16* hrow = g_h1b + ((size_t)h * NN + n) * FHID;
    const float* asrc = a1 + h * 2 * FHID;
    const float* adst = asrc + FHID;
    float s = 0.0f, d = 0.0f;
#pragma unroll
    for (int o = lane; o < FHID; o += 32) {
        float v = __bfloat162float(hrow[o]);
        s += v * asrc[o];
        d += v * adst[o];
    }
#pragma unroll
    for (int off = 16; off; off >>= 1) {
        s += __shfl_xor_sync(0xffffffffu, s, off);
        d += __shfl_xor_sync(0xffffffffu, d, off);
    }
    if (lane == 0) { g_esrc1[h*NN + n] = s; g_edst1[h*NN + n] = d; }
}

// ---------------- exp decomposition prep (PARALLEL: 16 blocks per head) -----
__global__ __launch_bounds__(256) void k_prep(int layer) {
    const int h     = (layer == 0) ? (blockIdx.x >> 4) : 0;
    const int slice = blockIdx.x & 15;
    const float *es, *ed;
    if (layer == 0) { es = g_esrc1 + h*NN; ed = g_edst1 + h*NN; }
    else            { es = g_esrc2;        ed = g_edst2; }

    __shared__ float red[8];
    const int tid = threadIdx.x, lane = tid & 31, wid = tid >> 5;
    float mx = -3.4e38f;
    const float4* ed4 = (const float4*)ed;
#pragma unroll 4
    for (int m = tid; m < NN/4; m += 256) {
        float4 v = ed4[m];
        mx = fmaxf(mx, fmaxf(fmaxf(v.x, v.y), fmaxf(v.z, v.w)));
    }
#pragma unroll
    for (int off = 16; off; off >>= 1) mx = fmaxf(mx, __shfl_xor_sync(0xffffffffu, mx, off));
    if (lane == 0) red[wid] = mx;
    __syncthreads();
    float maxed = red[0];
#pragma unroll
    for (int w = 1; w < 8; w++) maxed = fmaxf(maxed, red[w]);

    const int i = slice * 256 + tid;
    float e = es[i];
    float se = e + maxed;
    float rm = se >= 0.0f ? se : 0.2f * se;
    float a1 = __expf(e - rm);
    float a2 = __expf(0.2f * e - rm);
    float d = ed[i];
    float b1 = __expf(d);
    float b2 = __expf(0.2f * d);
    if (layer == 0) {
        g_A11[h*NN + i] = a1; g_A21[h*NN + i] = a2;
        uint32_t edb = (uint32_t)__bfloat16_as_ushort(__float2bfloat16(d));
        uint32_t b1b = (uint32_t)__bfloat16_as_ushort(__float2bfloat16(b1));
        uint32_t b2b = (uint32_t)__bfloat16_as_ushort(__float2bfloat16(b2));
        g_tab[h*NN + i] = make_uint2(edb | (b1b << 16), b2b);
    } else {
        g_A12[i] = a1; g_A22[i] = a2;
        g_B12[i] = b1; g_B22[i] = b2;
    }
}

// ---------------- fused attention GEMM (BM=128, BN=128, BK=64, 2 CTA/SM) ----
// Packed rank-1 table (8B/entry) in SMEM; gen reads uint4 pairs (LDS.128).
// SMEM (dynamic): As 2x128x72 @0 (36864B), Bs 2x64x136 @36864 (34816B),
//                 s_tab (uint2[4096]) @71680 (32768B)
#define ATTN_SMEM 104448

__global__ __launch_bounds__(256, 2) void k_attn_fused() {
    extern __shared__ char dsm[];
    __nv_bfloat16* As    = (__nv_bfloat16*)dsm;
    __nv_bfloat16* Bs    = (__nv_bfloat16*)(dsm + 36864);
    uint2*         s_tab = (uint2*)(dsm + 71680);

    __shared__ float s_zp[256];
    __shared__ float s_zi[128];

    const int h  = blockIdx.z;
    const int bm = blockIdx.x * 128;
    const int bn = blockIdx.y * 128;

    const int tid  = threadIdx.x;
    const int warp = tid >> 5, lane = tid & 31;
    const int wm = warp & 3, wn = warp >> 2;
    const int row = tid >> 1, half = tid & 1;   // gen: 2 threads/row, 32 cols each

    const float es  = g_esrc1[h*NN + bm + row];
    const float a1v = g_A11 [h*NN + bm + row];
    const float a2v = g_A21 [h*NN + bm + row];
    const unsigned* ab = g_adjbits + (size_t)(bm + row) * (NN/32) + half;
    const __nv_bfloat16* Bp = g_h1b + (size_t)h * NN * FHID;

    float acc[2][8][4];
#pragma unroll
    for (int t = 0; t < 2; t++)
#pragma unroll
        for (int j = 0; j < 8; j++)
#pragma unroll
            for (int i = 0; i < 4; i++) acc[t][j][i] = 0.0f;
    float zacc = 0.0f;

    auto loadB = [&](int buf, int k0) {
        __nv_bfloat16* Bb = Bs + buf * (64 * 136);
#pragma unroll
        for (int c0 = 0; c0 < 4; c0++) {
            int c = tid + c0 * 256;
            int br = c >> 4, bc = c & 15;
            cpa16(&Bb[br * 136 + bc * 8],
                  &Bp[(size_t)(k0 + br) * FHID + bn + bc * 8]);
        }
    };

    // gen: 32 p-values (cols half*32..half*32+31); table read as uint4 pairs
    auto gen = [&](int buf, int step, unsigned aw) {
        __nv_bfloat16* Ab = As + buf * (128 * 72);
        const int mb = step * 64 + half * 32;
        const uint4* tp = (const uint4*)(s_tab + mb);   // 16 pair-entries
#pragma unroll
        for (int g4 = 0; g4 < 4; g4++) {                // 8 cols per group
            __nv_bfloat162 q[4];
#pragma unroll
            for (int pr = 0; pr < 4; pr++) {            // pairs within group
                uint4 t = tp[g4 * 4 + pr];
                int j0 = g4 * 8 + pr * 2;
                float s0 = es + bf_lo(t.x);
                float p0 = (s0 >= 0.0f) ? a1v * bf_hi(t.x) : a2v * bf_lo(t.y);
                p0 = ((aw >> j0) & 1u) ? p0 : 0.0f;
                float s1 = es + bf_lo(t.z);
                float p1 = (s1 >= 0.0f) ? a1v * bf_hi(t.z) : a2v * bf_lo(t.w);
                p1 = ((aw >> (j0 + 1)) & 1u) ? p1 : 0.0f;
                zacc += p0 + p1;
                q[pr] = __floats2bfloat162_rn(p0, p1);
            }
            *(uint4*)&Ab[row * 72 + half * 32 + g4 * 8] = *(uint4*)q;
        }
    };

    const int S = NN / 64;   // 64 steps

    // ---- prologue ----
    loadB(0, 0); CP_COMMIT;
    {
        const uint4* t4 = (const uint4*)(g_tab + h*NN);
#pragma unroll
        for (int q = 0; q < 8; q++) ((uint4*)s_tab)[tid + q*256] = t4[tid + q*256];
    }
    __syncthreads();                   // table visible
    unsigned aw_nxt = ab[2];           // word for step 1
    gen(0, 0, ab[0]);
    CP_WAIT0; __syncthreads();         // Bs[0] + As[0] ready

    for (int k = 0; k < S; k++) {
        int cur = k & 1, nxt = cur ^ 1;
        if (k + 1 < S) {
            loadB(nxt, (k + 1) * 64);
            CP_COMMIT;
            gen(nxt, k + 1, aw_nxt);
            aw_nxt = (k + 2 < S) ? ab[2 * (k + 2)] : 0u;
        }
        mma_step64(As + cur * (128 * 72), Bs + cur * (64 * 136), wm, wn, lane, acc);
        CP_WAIT0; __syncthreads();
    }

    // ---- Z reduction (2 threads per row) ----
    s_zp[tid] = zacc;
    __syncthreads();
    if (tid < 128) s_zi[tid] = 1.0f / (s_zp[2*tid] + s_zp[2*tid + 1]);
    __syncthreads();

    // ---- epilogue: normalized bf16 out1 ----
    __nv_bfloat16* Cb = g_out1b + (size_t)h * NN * FHID;
#pragma unroll
    for (int t = 0; t < 2; t++) {
        int lr0 = wm * 32 + t * 16 + (lane >> 2);
        float iz0 = s_zi[lr0], iz1 = s_zi[lr0 + 8];
        int r0 = bm + lr0;
#pragma unroll
        for (int j = 0; j < 8; j++) {
            int col = bn + wn * 64 + j * 8 + (lane & 3) * 2;
            *(__nv_bfloat162*)&Cb[(size_t)r0 * FHID + col] =
                __floats2bfloat162_rn(acc[t][j][0] * iz0, acc[t][j][1] * iz0);
            *(__nv_bfloat162*)&Cb[(size_t)(r0 + 8) * FHID + col] =
                __floats2bfloat162_rn(acc[t][j][2] * iz1, acc[t][j][3] * iz1);
        }
    }
}

// ---------------- layer 2: fused mean/relu + feature GEMM + e2 dots ---------
__global__ __launch_bounds__(256) void k5_fused(const float* __restrict__ W2,
                                                const float* __restrict__ a2) {
    __shared__ float sW[FHID * FCLS];
    __shared__ float sH[16][FHID + 4];
    const int tid = threadIdx.x;
    const int n0 = blockIdx.x * 16;

    for (int i = tid; i < FHID * FCLS; i += 256) sW[i] = W2[i];

    {
        const int r  = tid >> 4;
        const int fb = (tid & 15) * 16;
        const int n  = n0 + r;
        float acc[16];
#pragma unroll
        for (int i = 0; i < 16; i++) acc[i] = 0.0f;
#pragma unroll
        for (int hh = 0; hh < NHD; hh++) {
            const __nv_bfloat162* src = (const __nv_bfloat162*)
                (g_out1b + ((size_t)(hh * NN + n)) * FHID + fb);
#pragma unroll
            for (int i = 0; i < 8; i++) {
                __nv_bfloat162 v = src[i];
                acc[2*i]     += __bfloat162float(v.x);
                acc[2*i + 1] += __bfloat162float(v.y);
            }
        }
#pragma unroll
        for (int i = 0; i < 16; i++) {
            float v = 0.25f * acc[i];
            sH[r][fb + i] = v > 0.0f ? v : 0.0f;
        }
    }
    __syncthreads();

    const int r = tid >> 4;
    const int o = tid & 15;
    const int n = n0 + r;
    float v = 0.0f;
#pragma unroll 8
    for (int f = 0; f < FHID; f++) v += sH[r][f] * sW[f * FCLS + o];
    g_h2[n * FCLS + o] = v;
    float vs = v * a2[o];
    float vd = v * a2[FCLS + o];
#pragma unroll
    for (int off = 8; off; off >>= 1) {
        vs += __shfl_xor_sync(0xffffffffu, vs, off);
        vd += __shfl_xor_sync(0xffffffffu, vd, off);
    }
    if (o == 0) { g_esrc2[n] = vs; g_edst2[n] = vd; }
}

// ---------------- layer 2 fused attention + log_softmax ---------------------
__global__ __launch_bounds__(256) void k7_fused(float* __restrict__ out) {
    const int n0 = blockIdx.x * 16;
    __shared__ float sh2[512 * 17];
    __shared__ float sed[512], sb1[512], sb2[512];
    __shared__ unsigned sbits[16][16];
    __shared__ float ses[16], sA1[16], sA2[16];
    const int tid = threadIdx.x;
    const int g = tid >> 4, l = tid & 15;
    if (tid < 16) {
        ses[tid] = g_esrc2[n0 + tid];
        sA1[tid] = g_A12[n0 + tid];
        sA2[tid] = g_A22[n0 + tid];
    }
    float acc[16];
#pragma unroll
    for (int o = 0; o < 16; o++) acc[o] = 0.0f;
    float z = 0.0f;

    for (int mt = 0; mt < 8; mt++) {
        __syncthreads();
#pragma unroll
        for (int j = 0; j < 32; j++) {
            int idx = tid + j * 256;
            int m = idx >> 4, o = idx & 15;
            sh2[m * 17 + o] = g_h2[(size_t)(mt*512 + m) * 16 + o];
        }
#pragma unroll
        for (int j = 0; j < 2; j++) {
            int m = tid + j * 256;
            sed[m] = g_edst2[mt*512 + m];
            sb1[m] = g_B12[mt*512 + m];
            sb2[m] = g_B22[mt*512 + m];
        }
        {
            int w = tid;
            if (w < 256) sbits[w >> 4][w & 15] =
                g_adjbits[(size_t)(n0 + (w >> 4)) * 128 + mt*16 + (w & 15)];
        }
        __syncthreads();
        float eg = ses[g], a1 = sA1[g], a2 = sA2[g];
#pragma unroll 4
        for (int k = 0; k < 32; k++) {
            int m = l + k * 16;
            float d = sed[m];
            float s = eg + d;
            float p = (s >= 0.0f) ? a1 * sb1[m] : a2 * sb2[m];
            if (!((sbits[g][m >> 5] >> (m & 31)) & 1)) p = 0.0f;
            z += p;
            const float* hp = &sh2[m * 17];
#pragma unroll
            for (int o = 0; o < 16; o++) acc[o] += p * hp[o];
        }
    }
#pragma unroll
    for (int off = 8; off; off >>= 1) {
        z += __shfl_xor_sync(0xffffffffu, z, off);
#pragma unroll
        for (int o = 0; o < 16; o++)
            acc[o] += __shfl_xor_sync(0xffffffffu, acc[o], off);
    }
    if (l == 0) {
        float inv = 1.0f / z;
        float t[16], mx = -3.4e38f;
#pragma unroll
        for (int o = 0; o < 16; o++) { t[o] = acc[o] * inv; mx = fmaxf(mx, t[o]); }
        float se = 0.0f;
#pragma unroll
        for (int o = 0; o < 16; o++) se += __expf(t[o] - mx);
        float lg = mx + __logf(se);
#pragma unroll
        for (int o = 0; o < 16; o++)
            out[(size_t)(n0 + g) * 16 + o] = t[o] - lg;
    }
}

// ---------------------------------------------------------------------------
extern "C" void kernel_launch(void* const* d_in, const int* in_sizes, int n_in,
                              void* d_out, int out_size) {
    const float* x   = (const float*)d_in[0];
    const int*   adj = (const int*)  d_in[1];
    const float* W1  = (const float*)d_in[2];
    const float* a1  = (const float*)d_in[3];
    const float* W2  = (const float*)d_in[4];
    const float* a2  = (const float*)d_in[5];
    float* out = (float*)d_out;

    cudaFuncSetAttribute(k1_mma, cudaFuncAttributeMaxDynamicSharedMemorySize, K1_SMEM);
    cudaFuncSetAttribute(k_attn_fused, cudaFuncAttributeMaxDynamicSharedMemorySize,
                         ATTN_SMEM);

    __nv_bfloat16* xb;  cudaGetSymbolAddress((void**)&xb,  g_xb);
    __nv_bfloat16* w1b; cudaGetSymbolAddress((void**)&w1b, g_W1b);

    const int NCVT = NN*FIN + NHD*FIN*FHID;
    k_cvt2<<<(NCVT + 255)/256, 256>>>(x, W1, xb, w1b);
    k_pack<<<(NN*NN/32)/8, 256>>>(adj);

    // layer 1
    dim3 gg(NN/128, FHID/128, NHD);              // 32 x 2 x 4 = 256 CTAs
    k1_mma<<<gg, 256, K1_SMEM>>>();
    k_edot<<<(NHD*NN)/8, 256>>>(a1);
    k_prep<<<NHD * 16, 256>>>(0);                // 64 blocks (parallel)
    dim3 ga(NN/128, FHID/128, NHD);              // 32 x 2 x 4 = 256 CTAs
    k_attn_fused<<<ga, 256, ATTN_SMEM>>>();

    // layer 2
    k5_fused<<<NN/16, 256>>>(W2, a2);
    k_prep<<<16, 256>>>(1);
    k7_fused<<<NN/16, 256>>>(out);
}